// round 9
// baseline (speedup 1.0000x reference)
#include <cuda_runtime.h>
#include <cstdint>

#define T_STEPS 2048
#define BATCH   64
#define IN_DIM  128
#define HDIM    256
#define OUT_DIM 128
#define NTHR    512
#define NBLK    128           // 16 groups (4 batch rows) x 8 ranks (32 h-cols)
#define WOPAD   272

// smem layout (floats)
#define OFF_ACT   0                       // [2][384][4]  = 3072
#define OFF_WOUT  3072                    // [16][272]    = 4352
#define OFF_G     7424                    // [128][4]     = 512
#define OFF_BIAS  7936                    // 128
#define OFF_BOUT  8064                    // 16
#define SMEM_FLOATS 8080
#define SMEM_BYTES (SMEM_FLOATS * 4)      // 32320

// persistent state: transposed h, double-buffered per group
__device__ float g_hT[16][2][HDIM * 4];   // [grp][buf][col*4 + r]
struct Flag { unsigned v; unsigned pad[31]; };
__device__ Flag g_flags[NBLK];

__device__ __forceinline__ unsigned ld_acq(const unsigned* p) {
    unsigned v;
    asm volatile("ld.acquire.gpu.global.u32 %0, [%1];" : "=r"(v) : "l"(p) : "memory");
    return v;
}
__device__ __forceinline__ void st_rel(unsigned* p, unsigned v) {
    asm volatile("st.release.gpu.global.u32 [%0], %1;" :: "l"(p), "r"(v) : "memory");
}

__global__ void __launch_bounds__(NTHR, 1) lstm_swift_kernel(
    const float* __restrict__ input,   // [T, B, IN]
    const float* __restrict__ W_ih,    // [4H, IN]
    const float* __restrict__ W_hh,    // [4H, H]
    const float* __restrict__ b_ih,    // [4H]
    const float* __restrict__ b_hh,    // [4H]
    const float* __restrict__ W_out,   // [OUT, H]
    const float* __restrict__ b_out,   // [OUT]
    float* __restrict__ out,
    int out_size)
{
    extern __shared__ float sm[];
    float* sAct  = sm + OFF_ACT;   // [buf][k][r]: k<128 x, k>=128 h
    float* sWo   = sm + OFF_WOUT;
    float* sG    = sm + OFF_G;     // gates [m][r]
    float* sBias = sm + OFF_BIAS;
    float* sBOut = sm + OFF_BOUT;

    const int tid  = threadIdx.x;
    const int bid  = blockIdx.x;
    const int grp  = bid >> 3;
    const int rank = bid & 7;
    const int rbase = grp * 4;
    const int cb    = rank * 32;

    const unsigned base = ld_acq(&g_flags[bid].v);   // flags uniform at start

    // ---- gate-GEMM mapping: m = gate-col (tid>>2), kq = split-K (tid&3) ----
    const int m   = tid >> 2;
    const int kq  = tid & 3;
    const int g_  = m >> 5;
    const int col = m & 31;
    const int grow = g_ * HDIM + cb + col;

    // ---- weights in registers: 32 x-weights (kq*32) + 64 h-weights (kq*64) ----
    float wreg[96];
    {
        const float* src_ih = W_ih + (size_t)grow * IN_DIM + kq * 32;
        const float* src_hh = W_hh + (size_t)grow * HDIM + kq * 64;
        #pragma unroll
        for (int i = 0; i < 32; i++) wreg[i] = __ldg(src_ih + i);
        #pragma unroll
        for (int i = 0; i < 64; i++) wreg[32 + i] = __ldg(src_hh + i);
    }

    // ---- smem preload ----
    for (int i = tid; i < 16 * HDIM; i += NTHR) {
        int o = i >> 8, k = i & 255;
        sWo[o * WOPAD + k] = W_out[(rank * 16 + o) * HDIM + k];
    }
    if (tid < 128) {
        int gi = tid >> 5, ci = tid & 31;
        int gr = gi * HDIM + cb + ci;
        sBias[tid] = b_ih[gr] + b_hh[gr];
    }
    if (tid < 16) sBOut[tid] = b_out[rank * 16 + tid];

    // zero both act buffers (h_0 = 0), x_0 transposed into buf0
    for (int i = tid; i < 2 * 384 * 4; i += NTHR) sAct[i] = 0.0f;
    __syncthreads();
    if (tid < 128) {
        int r = tid >> 5, k5 = tid & 31;
        float4 v = *(const float4*)(input + ((size_t)rbase + r) * IN_DIM + k5 * 4);
        sAct[(k5 * 4 + 0) * 4 + r] = v.x;
        sAct[(k5 * 4 + 1) * 4 + r] = v.y;
        sAct[(k5 * 4 + 2) * 4 + r] = v.z;
        sAct[(k5 * 4 + 3) * 4 + r] = v.w;
    }
    __syncthreads();

    const size_t Y_TOTAL = (size_t)T_STEPS * BATCH * OUT_DIM;
    const bool write_tail = (out_size >= (int)(Y_TOTAL + 2 * BATCH * HDIM));

    float c_reg = 0.0f;   // cell state (r=tid>>5, c=tid&31), threads 0-127

    for (int t = 0; t < T_STEPS; t++) {
        const int buf = t & 1;
        float* A  = sAct + buf * 1536;
        float* An = sAct + (1 - buf) * 1536;

        // ---- phase 1: x_{t+1} LDG issued early (threads 128-255) ----
        float4 xv = make_float4(0.f, 0.f, 0.f, 0.f);
        const int idx2 = tid - 128;
        if (tid >= 128 && tid < 256 && t + 1 < T_STEPS) {
            int xr = idx2 >> 5, xk5 = idx2 & 31;
            xv = __ldcg((const float4*)(input
                    + ((size_t)(t + 1) * BATCH + rbase + xr) * IN_DIM + xk5 * 4));
        }

        // ---- phase 2: x-part GEMM (K=128 split 4 ways; off critical path) ----
        unsigned long long acc01 = 0ULL, acc23 = 0ULL;
        {
            const ulonglong2* av = (const ulonglong2*)(A + kq * 128);
            #pragma unroll
            for (int i = 0; i < 32; i++) {
                ulonglong2 p = av[i];
                unsigned wu = __float_as_uint(wreg[i]);
                unsigned long long wp;
                asm("mov.b64 %0, {%1, %1};" : "=l"(wp) : "r"(wu));
                asm("fma.rn.f32x2 %0, %1, %2, %0;" : "+l"(acc01) : "l"(wp), "l"(p.x));
                asm("fma.rn.f32x2 %0, %1, %2, %0;" : "+l"(acc23) : "l"(wp), "l"(p.y));
            }
        }

        // ---- phase 3: store x_{t+1} (threads 128-255) ----
        if (tid >= 128 && tid < 256 && t + 1 < T_STEPS) {
            int xr = idx2 >> 5, xk5 = idx2 & 31;
            An[(xk5 * 4 + 0) * 4 + xr] = xv.x;
            An[(xk5 * 4 + 1) * 4 + xr] = xv.y;
            An[(xk5 * 4 + 2) * 4 + xr] = xv.z;
            An[(xk5 * 4 + 3) * 4 + xr] = xv.w;
        }

        // ---- phase 4: per-rank poll + fill h_t (threads 256-511) ----
        if (tid >= 256 && t > 0) {
            const int idx = tid - 256;                 // h-col 0..255
            const unsigned* fp = &g_flags[grp * 8 + (idx >> 5)].v;
            while (ld_acq(fp) < base + (unsigned)t) { }
            float4 v = __ldcg(((const float4*)g_hT[grp][buf]) + idx);
            ((float4*)A)[128 + idx] = v;
        }
        __syncthreads();

        // ---- phase 5: h-part GEMM (K=256 split 4 ways; critical path) ----
        {
            const ulonglong2* av = (const ulonglong2*)(A + 512 + kq * 256);
            #pragma unroll
            for (int i = 0; i < 64; i++) {
                ulonglong2 p = av[i];
                unsigned wu = __float_as_uint(wreg[32 + i]);
                unsigned long long wp;
                asm("mov.b64 %0, {%1, %1};" : "=l"(wp) : "r"(wu));
                asm("fma.rn.f32x2 %0, %1, %2, %0;" : "+l"(acc01) : "l"(wp), "l"(p.x));
                asm("fma.rn.f32x2 %0, %1, %2, %0;" : "+l"(acc23) : "l"(wp), "l"(p.y));
            }
        }

        // ---- phase 6: split-K reduce via shfl over kq lanes; kq0 writes sG ----
        {
            unsigned u0, u1, u2, u3;
            asm("mov.b64 {%0, %1}, %2;" : "=r"(u0), "=r"(u1) : "l"(acc01));
            asm("mov.b64 {%0, %1}, %2;" : "=r"(u2), "=r"(u3) : "l"(acc23));
            float f0 = __uint_as_float(u0), f1 = __uint_as_float(u1);
            float f2 = __uint_as_float(u2), f3 = __uint_as_float(u3);
            f0 += __shfl_xor_sync(0xffffffffu, f0, 1);
            f1 += __shfl_xor_sync(0xffffffffu, f1, 1);
            f2 += __shfl_xor_sync(0xffffffffu, f2, 1);
            f3 += __shfl_xor_sync(0xffffffffu, f3, 1);
            f0 += __shfl_xor_sync(0xffffffffu, f0, 2);
            f1 += __shfl_xor_sync(0xffffffffu, f1, 2);
            f2 += __shfl_xor_sync(0xffffffffu, f2, 2);
            f3 += __shfl_xor_sync(0xffffffffu, f3, 2);
            if (kq == 0) {
                float b = sBias[m];
                *(float4*)(sG + m * 4) = make_float4(f0 + b, f1 + b, f2 + b, f3 + b);
            }
        }
        __syncthreads();

        const unsigned tgt = base + 1 + (unsigned)t;

        // ---- phase 7: cell + release (warps 0-3) || y_{t-1} (warps 8-15) ----
        if (tid < 128) {
            const int r = tid >> 5, c = tid & 31;
            float gi = sG[(0 * 32 + c) * 4 + r];
            float gf = sG[(1 * 32 + c) * 4 + r];
            float gg = sG[(2 * 32 + c) * 4 + r];
            float go = sG[(3 * 32 + c) * 4 + r];
            float i_ = 1.0f / (1.0f + __expf(-gi));
            float f_ = 1.0f / (1.0f + __expf(-gf));
            float gv = tanhf(gg);
            float o_ = 1.0f / (1.0f + __expf(-go));
            float cn = f_ * c_reg + i_ * gv;
            float hn = o_ * tanhf(cn);
            c_reg = cn;

            __stcg(&g_hT[grp][1 - buf][(cb + c) * 4 + r], hn);

            if (t == T_STEPS - 1 && write_tail) {
                out[Y_TOTAL + (size_t)(rbase + r) * HDIM + cb + c] = hn;
                out[Y_TOTAL + BATCH * HDIM + (size_t)(rbase + r) * HDIM + cb + c] = cn;
            }
            asm volatile("bar.sync 1, 128;" ::: "memory");
            if (tid == 0) st_rel(&g_flags[bid].v, tgt);
        } else if (tid >= 256 && t > 0) {
            const int slot = tid - 256;
            const int o = slot >> 4, ks = slot & 15;
            float y0 = 0.f, y1 = 0.f, y2 = 0.f, y3 = 0.f;
            const float* wo = sWo + o * WOPAD + ks;
            const float4* ah = ((const float4*)A) + 128 + ks;
            #pragma unroll
            for (int i = 0; i < 16; i++) {
                float w = wo[i * 16];
                float4 hv = ah[i * 16];
                y0 += w * hv.x; y1 += w * hv.y; y2 += w * hv.z; y3 += w * hv.w;
            }
            #pragma unroll
            for (int s = 1; s <= 8; s <<= 1) {
                y0 += __shfl_xor_sync(0xffffffffu, y0, s);
                y1 += __shfl_xor_sync(0xffffffffu, y1, s);
                y2 += __shfl_xor_sync(0xffffffffu, y2, s);
                y3 += __shfl_xor_sync(0xffffffffu, y3, s);
            }
            if (ks == 0) {
                float b = sBOut[o];
                size_t yb = ((size_t)(t - 1) * BATCH + rbase) * OUT_DIM
                            + (size_t)rank * 16 + o;
                out[yb + 0 * OUT_DIM] = y0 + b;
                out[yb + 1 * OUT_DIM] = y1 + b;
                out[yb + 2 * OUT_DIM] = y2 + b;
                out[yb + 3 * OUT_DIM] = y3 + b;
            }
        }
        // no trailing syncthreads: next-step hazards all covered by the
        // phase-4 and phase-6 barriers (buffers alternate; see analysis)
    }

    // ---- tail: y_{T-1} from h_T (g_hT[grp][0], flags reach base+2048) ----
    {
        float* A = sAct;   // buf 0 = T_STEPS & 1 ^ ... (T even -> buf0)
        if (tid >= 256) {
            const int idx = tid - 256;
            const unsigned* fp = &g_flags[grp * 8 + (idx >> 5)].v;
            while (ld_acq(fp) < base + (unsigned)T_STEPS) { }
            float4 v = __ldcg(((const float4*)g_hT[grp][0]) + idx);
            ((float4*)A)[128 + idx] = v;
        }
        __syncthreads();
        if (tid >= 256) {
            const int slot = tid - 256;
            const int o = slot >> 4, ks = slot & 15;
            float y0 = 0.f, y1 = 0.f, y2 = 0.f, y3 = 0.f;
            const float* wo = sWo + o * WOPAD + ks;
            const float4* ah = ((const float4*)A) + 128 + ks;
            #pragma unroll
            for (int i = 0; i < 16; i++) {
                float w = wo[i * 16];
                float4 hv = ah[i * 16];
                y0 += w * hv.x; y1 += w * hv.y; y2 += w * hv.z; y3 += w * hv.w;
            }
            #pragma unroll
            for (int s = 1; s <= 8; s <<= 1) {
                y0 += __shfl_xor_sync(0xffffffffu, y0, s);
                y1 += __shfl_xor_sync(0xffffffffu, y1, s);
                y2 += __shfl_xor_sync(0xffffffffu, y2, s);
                y3 += __shfl_xor_sync(0xffffffffu, y3, s);
            }
            if (ks == 0) {
                float b = sBOut[o];
                size_t yb = ((size_t)(T_STEPS - 1) * BATCH + rbase) * OUT_DIM
                            + (size_t)rank * 16 + o;
                out[yb + 0 * OUT_DIM] = y0 + b;
                out[yb + 1 * OUT_DIM] = y1 + b;
                out[yb + 2 * OUT_DIM] = y2 + b;
                out[yb + 3 * OUT_DIM] = y3 + b;
            }
        }
    }
}

extern "C" void kernel_launch(void* const* d_in, const int* in_sizes, int n_in,
                              void* d_out, int out_size) {
    const float* input = (const float*)d_in[0];
    const float* W_ih  = (const float*)d_in[1];
    const float* W_hh  = (const float*)d_in[2];
    const float* b_ih  = (const float*)d_in[3];
    const float* b_hh  = (const float*)d_in[4];
    const float* W_out = (const float*)d_in[5];
    const float* b_out = (const float*)d_in[6];
    float* out = (float*)d_out;
    (void)in_sizes; (void)n_in;

    cudaFuncSetAttribute(lstm_swift_kernel,
                         cudaFuncAttributeMaxDynamicSharedMemorySize, SMEM_BYTES);
    lstm_swift_kernel<<<NBLK, NTHR, SMEM_BYTES>>>(
        input, W_ih, W_hh, b_ih, b_hh, W_out, b_out, out, out_size);
}